// round 8
// baseline (speedup 1.0000x reference)
#include <cuda_runtime.h>
#include <math.h>

#define N_POINTS 128
#define STEPS    50
#define N_EVENTS 10000
#define DT       2.0f
#define SQRT_PI_F 1.7724539f

#define N_PAIRS    ((N_POINTS * (N_POINTS - 1)) / 2)      // 8128
#define PAIR_TOTAL (N_PAIRS * STEPS)                      // 406400
#define TOTAL_WORK (PAIR_TOTAL + N_EVENTS)                // 416400

#define BLOCKS  592
#define THREADS 256
#define CHUNK   3                                         // 592*256*3 >= TOTAL_WORK

// ---- device scratch (allocation-free contract) ----
__device__ float g_Z[2 * N_POINTS * STEPS];               // [row = point*2+dim][s]
__device__ float g_ts[STEPS + 1];                         // ts[s]; slot 50 = times[M-1]
__device__ float g_vl[STEPS];                             // valid mask (0/1)
__device__ unsigned int g_flag  = 0;                      // tables-ready flag
__device__ unsigned int g_count = 0;
__device__ double       g_acc   = 0.0;

__device__ __forceinline__ int tri_base(int i) {          // # pairs before row i
    return i * (N_POINTS - 1) - (i * (i - 1)) / 2;
}

// Abramowitz-Stegun 7.1.26: |err| < 1.5e-7
__device__ __forceinline__ float fast_erff(float x) {
    float ax = fabsf(x);
    float t  = __fdividef(1.0f, fmaf(0.3275911f, ax, 1.0f));
    float poly = t * fmaf(t, fmaf(t, fmaf(t, fmaf(t, 1.061405429f,
                    -1.453152027f), 1.421413741f), -0.284496736f), 0.254829592f);
    float r = 1.0f - poly * __expf(-ax * ax);
    return copysignf(r, x);
}

__global__ void __launch_bounds__(THREADS)
fused_kernel(const float* __restrict__ data,
             const float* __restrict__ beta,
             const float* __restrict__ z0,
             const float* __restrict__ v0,
             float* __restrict__ out) {
    const int   tid   = threadIdx.x;
    const float denom = DT + DT * 0.001f;                 // 2.002f, matches ref rounding
    const float b0    = __ldg(&beta[0]);

    __shared__ double sRd[THREADS / 32];

    if (blockIdx.x == 0) {
        // ================= producer block: compute tables ONCE =================
        float tlast = __ldg(&data[(N_EVENTS - 1) * 3 + 2]);
        if (tid <= STEPS) {
            g_ts[tid] = tlast;                            // empty segment -> times[M-1]
            if (tid < STEPS) g_vl[tid] = 0.0f;
        }
        // Z cumsum: one row per thread (exactly 256 rows)
        {
            float z = __ldg(&z0[tid]);
            const float* vr = v0 + tid * STEPS;
            float* Zr = g_Z + tid * STEPS;
            Zr[0] = z;                                    // Z_steps[0] = z0
            float cum = 0.0f;
            #pragma unroll
            for (int s = 1; s < STEPS; ++s) {
                cum += z + vr[s - 1] * DT;                // Z_steps[s]
                Zr[s] = cum;
            }
        }
        __syncthreads();                                  // defaults before scan overwrite
        // boundary scan over sorted event times (independent loads, MLP-hidden)
        for (int m = tid; m < N_EVENTS; m += THREADS) {
            float t   = data[m * 3 + 2];
            int   idx = (int)floorf(t / denom);
            int newseg = (m == 0) ||
                         (((int)floorf(data[m * 3 - 1] / denom)) != idx);
            if (newseg) { g_ts[idx] = t; g_vl[idx] = 1.0f; }
        }
        __syncthreads();
        if (tid == 0) {
            __threadfence();                              // release tables
            *((volatile unsigned int*)&g_flag) = 1u;      // plain store, no atomic RMW
        }
        __syncthreads();
    } else {
        // ===== consumer blocks: wait via plain volatile loads (no atomic RMW) =====
        if (tid == 0) {
            while (*((volatile unsigned int*)&g_flag) == 0u) __nanosleep(64);
            __threadfence();                              // acquire
        }
        __syncthreads();
    }

    // ---- main phase: contiguous chunk of terms per thread ----
    double local = 0.0;
    int t0 = (blockIdx.x * THREADS + tid) * CHUNK;
    if (t0 < TOTAL_WORK) {
        int i = 0, j = 1, s = 0;
        if (t0 < PAIR_TOTAL) {                            // triangular decode + fixup
            int p = t0 / STEPS;
            s = t0 - p * STEPS;
            float disc = (float)(255 * 255 - 8 * p);
            i = (int)((255.0f - sqrtf(disc)) * 0.5f);
            i = min(max(i, 0), N_POINTS - 2);
            while (i < N_POINTS - 2 && tri_base(i + 1) <= p) ++i;
            while (i > 0 && tri_base(i) > p) --i;
            j = i + 1 + (p - tri_base(i));
        }

        #pragma unroll
        for (int k = 0; k < CHUNK; ++k) {
            int q = t0 + k;
            if (q >= TOTAL_WORK) break;
            if (q < PAIR_TOTAL) {
                int oi = i * 100 + s, oj = j * 100 + s;
                float dzx = __ldg(&g_Z[oi])      - __ldg(&g_Z[oj]);
                float dzy = __ldg(&g_Z[oi + 50]) - __ldg(&g_Z[oj + 50]);
                float dvx = __ldg(&v0[oi])       - __ldg(&v0[oj]);
                float dvy = __ldg(&v0[oi + 50])  - __ldg(&v0[oj + 50]);

                float a = fmaxf(dvx * dvx + dvy * dvy, 1e-10f);
                float b = 2.0f * (dzx * dvx + dzy * dvy);
                float c = dzx * dzx + dzy * dzy;
                float rsa    = rsqrtf(a);
                float inv2sa = 0.5f * rsa;
                float shift  = b * inv2sa;
                float arg    = b0 - c + shift * shift;
                if (arg > -25.0f) {                       // exp-underflow skip
                    float sa  = a * rsa;
                    float ts  = __ldg(&g_ts[s]);
                    float tf  = __ldg(&g_ts[s + 1]);
                    float loa = fmaf(sa, ts, shift);
                    float hia = fmaf(sa, tf, shift);
                    if (loa < 5.0f && hia > -5.0f) {      // erf-saturation skip
                        float pref  = SQRT_PI_F * inv2sa * __expf(arg);
                        float integ = pref * (fast_erff(hia) - fast_erff(loa));
                        local -= (double)(integ * __ldg(&g_vl[s]));
                    }
                }
                if (++s == STEPS) {                       // advance (i,j,s)
                    s = 0;
                    if (++j == N_POINTS) { ++i; j = i + 1; }
                }
            } else {
                int e = q - PAIR_TOTAL;
                float si = data[e * 3], dj = data[e * 3 + 1], t = data[e * 3 + 2];
                int ii = (int)si, jj = (int)dj;
                float stepf = floorf(t / denom);
                int   id    = (int)stepf;
                float delta = t - stepf * DT;
                int oi = ii * 100 + id, oj = jj * 100 + id;
                float dx = (__ldg(&g_Z[oi])      + __ldg(&v0[oi])      * delta)
                         - (__ldg(&g_Z[oj])      + __ldg(&v0[oj])      * delta);
                float dy = (__ldg(&g_Z[oi + 50]) + __ldg(&v0[oi + 50]) * delta)
                         - (__ldg(&g_Z[oj + 50]) + __ldg(&v0[oj + 50]) * delta);
                local += (double)(b0 - (dx * dx + dy * dy));
            }
        }
    }

    // ---- reduction: warp shuffle -> smem -> warp0 -> global atomic ----
    double v = local;
    #pragma unroll
    for (int off = 16; off > 0; off >>= 1)
        v += __shfl_down_sync(0xffffffffu, v, off);
    int warp = tid >> 5, lane = tid & 31;
    if (lane == 0) sRd[warp] = v;
    __syncthreads();
    if (warp == 0) {
        v = (lane < THREADS / 32) ? sRd[lane] : 0.0;
        #pragma unroll
        for (int off = 4; off > 0; off >>= 1)
            v += __shfl_down_sync(0xffffffffu, v, off);
        if (lane == 0) {
            atomicAdd(&g_acc, v);
            __threadfence();
            unsigned int old = atomicAdd(&g_count, 1u);
            if (old == gridDim.x - 1) {                   // last block: write + reset
                double total = atomicAdd(&g_acc, 0.0);
                out[0] = (float)total;
                g_acc   = 0.0;
                g_count = 0u;
                g_flag  = 0u;                             // reset for next graph replay
            }
        }
    }
}

// Inputs (metadata order): data[30000], t0[1], tn[1], beta[1], z0[256], v0[12800]
extern "C" void kernel_launch(void* const* d_in, const int* in_sizes, int n_in,
                              void* d_out, int out_size) {
    const float* data = (const float*)d_in[0];
    const float* beta = (const float*)d_in[3];
    const float* z0   = (const float*)d_in[4];
    const float* v0   = (const float*)d_in[5];
    float* out = (float*)d_out;

    fused_kernel<<<BLOCKS, THREADS>>>(data, beta, z0, v0, out);
}

// round 9
// speedup vs baseline: 1.7766x; 1.7766x over previous
#include <cuda_runtime.h>
#include <math.h>

#define N_POINTS 128
#define STEPS    50
#define N_EVENTS 10000
#define DT       2.0f
#define SQRT_PI_F 1.7724539f
#define PAD_S    52                                       // padded step stride (f4-aligned)
#define N_GROUPS 13                                       // 13 groups of 4 steps (48..51 masked)

#define N_PAIRS      ((N_POINTS * (N_POINTS - 1)) / 2)    // 8128
#define PAIR_THREADS (N_PAIRS * N_GROUPS)                 // 105664
#define MAIN_THREADS 256
#define MAIN_BLOCKS  ((PAIR_THREADS + N_EVENTS + MAIN_THREADS - 1) / MAIN_THREADS)  // 452

// ---- device scratch (allocation-free contract) ----
__device__ __align__(16) float  g_Zx[N_POINTS * PAD_S];
__device__ __align__(16) float  g_Zy[N_POINTS * PAD_S];
__device__ __align__(16) float  g_Vx[N_POINTS * PAD_S];
__device__ __align__(16) float  g_Vy[N_POINTS * PAD_S];
__device__ __align__(16) float2 g_tstf[PAD_S];            // (ts', tf'); tf'==ts' when invalid
__device__ double       g_acc   = 0.0;
__device__ unsigned int g_count = 0;

__device__ __forceinline__ int tri_base(int i) {          // # pairs before row i
    return i * (N_POINTS - 1) - (i * (i - 1)) / 2;
}

// Abramowitz-Stegun 7.1.26: |err| < 1.5e-7
__device__ __forceinline__ float fast_erff(float x) {
    float ax = fabsf(x);
    float t  = __fdividef(1.0f, fmaf(0.3275911f, ax, 1.0f));
    float poly = t * fmaf(t, fmaf(t, fmaf(t, fmaf(t, 1.061405429f,
                    -1.453152027f), 1.421413741f), -0.284496736f), 0.254829592f);
    float r = 1.0f - poly * __expf(-ax * ax);
    return copysignf(r, x);
}

// ---------------------------------------------------------------------------
// Kernel A: 1 block x 1024. Padded-SoA Z cumsum + V copy + ts/tf table.
// ---------------------------------------------------------------------------
__global__ void __launch_bounds__(1024)
prep_kernel(const float* __restrict__ data,
            const float* __restrict__ z0,
            const float* __restrict__ v0) {
    __shared__ float sTs[STEPS + 1];
    __shared__ float sVl[STEPS];
    const int   tid   = threadIdx.x;
    const float denom = DT + DT * 0.001f;                 // 2.002f, matches ref rounding
    const float tlast = __ldg(&data[(N_EVENTS - 1) * 3 + 2]);

    if (tid <= STEPS) {
        sTs[tid] = tlast;                                 // empty segment -> times[M-1]
        if (tid < STEPS) sVl[tid] = 0.0f;
    }
    __syncthreads();

    // Z cumsum into padded SoA: one (point,dim) row per thread
    if (tid < 2 * N_POINTS) {
        int p = tid >> 1, d = tid & 1;
        float* Zr = (d ? g_Zy : g_Zx) + p * PAD_S;
        float* Vr = (d ? g_Vy : g_Vx) + p * PAD_S;
        const float* vr = v0 + tid * STEPS;               // v0 row = p*2 + d
        float z = __ldg(&z0[tid]);
        Zr[0] = z;                                        // Z_steps[0] = z0
        float cum = 0.0f;
        #pragma unroll
        for (int s = 1; s < STEPS; ++s) {
            cum += z + vr[s - 1] * DT;                    // Z_steps[s] (same fp order as ref)
            Zr[s] = cum;
        }
        Zr[50] = 0.0f; Zr[51] = 0.0f;                     // pad (masked in main)
        Vr[50] = 0.0f; Vr[51] = 0.0f;
    }
    // V copy into padded SoA
    for (int idx = tid; idx < 2 * N_POINTS * STEPS; idx += 1024) {
        int row = idx / STEPS, s = idx - row * STEPS;
        int p = row >> 1, d = row & 1;
        ((d ? g_Vy : g_Vx) + p * PAD_S)[s] = v0[idx];
    }
    // segment-boundary scan over sorted times (10 iters/thread, independent loads)
    for (int m = tid; m < N_EVENTS; m += 1024) {
        float t   = data[m * 3 + 2];
        int   idx = (int)floorf(t / denom);
        int newseg = (m == 0) ||
                     (((int)floorf(data[m * 3 - 1] / denom)) != idx);
        if (newseg) { sTs[idx] = t; sVl[idx] = 1.0f; }
    }
    __syncthreads();
    if (tid < STEPS) {
        float tsA = sTs[tid];
        float tfA = (sVl[tid] != 0.0f) ? sTs[tid + 1] : tsA;  // invalid -> ts==tf -> term 0
        g_tstf[tid] = make_float2(tsA, tfA);
    } else if (tid < PAD_S) {
        g_tstf[tid] = make_float2(0.0f, 0.0f);
    }
}

// ---------------------------------------------------------------------------
// Kernel B: one (pair, 4-step group) per thread, float4 loads; + event threads.
// ---------------------------------------------------------------------------
union F4 { float4 v; float a[4]; };

__global__ void __launch_bounds__(MAIN_THREADS, 4)
main_kernel(const float* __restrict__ data,
            const float* __restrict__ beta,
            float* __restrict__ out) {
    const int   gid = blockIdx.x * MAIN_THREADS + threadIdx.x;
    const float b0  = __ldg(&beta[0]);
    double local = 0.0;

    if (gid < PAIR_THREADS) {
        int p  = gid / N_GROUPS;
        int s0 = (gid - p * N_GROUPS) * 4;
        // triangular decode + fixup
        float disc = (float)(255 * 255 - 8 * p);
        int i = (int)((255.0f - sqrtf(disc)) * 0.5f);
        i = min(max(i, 0), N_POINTS - 2);
        while (i < N_POINTS - 2 && tri_base(i + 1) <= p) ++i;
        while (i > 0 && tri_base(i) > p) --i;
        int j = i + 1 + (p - tri_base(i));

        const int oi = i * PAD_S + s0, oj = j * PAD_S + s0;
        F4 zxi, zyi, zxj, zyj, vxi, vyi, vxj, vyj, tA, tB;
        zxi.v = __ldg((const float4*)(g_Zx + oi));
        zyi.v = __ldg((const float4*)(g_Zy + oi));
        zxj.v = __ldg((const float4*)(g_Zx + oj));
        zyj.v = __ldg((const float4*)(g_Zy + oj));
        vxi.v = __ldg((const float4*)(g_Vx + oi));
        vyi.v = __ldg((const float4*)(g_Vy + oi));
        vxj.v = __ldg((const float4*)(g_Vx + oj));
        vyj.v = __ldg((const float4*)(g_Vy + oj));
        tA.v  = __ldg((const float4*)(&g_tstf[s0]));      // (ts,tf) for s0, s0+1
        tB.v  = __ldg((const float4*)(&g_tstf[s0]) + 1);  // (ts,tf) for s0+2, s0+3

        #pragma unroll
        for (int k = 0; k < 4; ++k) {
            if (s0 + k < STEPS) {                         // masks pad steps 50,51
                float dzx = zxi.a[k] - zxj.a[k];
                float dzy = zyi.a[k] - zyj.a[k];
                float dvx = vxi.a[k] - vxj.a[k];
                float dvy = vyi.a[k] - vyj.a[k];

                float a = fmaxf(dvx * dvx + dvy * dvy, 1e-10f);
                float b = 2.0f * (dzx * dvx + dzy * dvy);
                float c = dzx * dzx + dzy * dzy;
                float rsa    = rsqrtf(a);
                float inv2sa = 0.5f * rsa;
                float shift  = b * inv2sa;
                float arg    = b0 - c + shift * shift;
                if (arg > -25.0f) {                       // exp-underflow skip
                    float sa = a * rsa;
                    float ts = (k < 2) ? ((k == 0) ? tA.a[0] : tA.a[2])
                                       : ((k == 2) ? tB.a[0] : tB.a[2]);
                    float tf = (k < 2) ? ((k == 0) ? tA.a[1] : tA.a[3])
                                       : ((k == 2) ? tB.a[1] : tB.a[3]);
                    float loa = fmaf(sa, ts, shift);
                    float hia = fmaf(sa, tf, shift);
                    if (loa < 5.0f && hia > -5.0f) {      // erf-saturation skip
                        float pref  = SQRT_PI_F * inv2sa * __expf(arg);
                        local -= (double)(pref * (fast_erff(hia) - fast_erff(loa)));
                    }
                }
            }
        }
    } else if (gid - PAIR_THREADS < N_EVENTS) {
        int e = gid - PAIR_THREADS;
        const float denom = DT + DT * 0.001f;
        float si = __ldg(&data[e * 3]);
        float dj = __ldg(&data[e * 3 + 1]);
        float t  = __ldg(&data[e * 3 + 2]);
        int ii = (int)si, jj = (int)dj;
        float stepf = floorf(t / denom);
        int   id    = (int)stepf;
        float delta = t - stepf * DT;
        int oi = ii * PAD_S + id, oj = jj * PAD_S + id;
        float dx = (__ldg(&g_Zx[oi]) + __ldg(&g_Vx[oi]) * delta)
                 - (__ldg(&g_Zx[oj]) + __ldg(&g_Vx[oj]) * delta);
        float dy = (__ldg(&g_Zy[oi]) + __ldg(&g_Vy[oi]) * delta)
                 - (__ldg(&g_Zy[oj]) + __ldg(&g_Vy[oj]) * delta);
        local += (double)(b0 - (dx * dx + dy * dy));
    }

    // ---- reduction: warp shuffle -> smem -> warp0 -> global atomic ----
    __shared__ double sRd[MAIN_THREADS / 32];
    double v = local;
    #pragma unroll
    for (int off = 16; off > 0; off >>= 1)
        v += __shfl_down_sync(0xffffffffu, v, off);
    int warp = threadIdx.x >> 5, lane = threadIdx.x & 31;
    if (lane == 0) sRd[warp] = v;
    __syncthreads();
    if (warp == 0) {
        v = (lane < MAIN_THREADS / 32) ? sRd[lane] : 0.0;
        #pragma unroll
        for (int off = 4; off > 0; off >>= 1)
            v += __shfl_down_sync(0xffffffffu, v, off);
        if (lane == 0) {
            atomicAdd(&g_acc, v);
            __threadfence();
            unsigned int old = atomicAdd(&g_count, 1u);
            if (old == gridDim.x - 1) {                   // last block: write + reset
                double total = atomicAdd(&g_acc, 0.0);
                out[0] = (float)total;
                g_acc   = 0.0;
                g_count = 0u;
            }
        }
    }
}

// Inputs (metadata order): data[30000], t0[1], tn[1], beta[1], z0[256], v0[12800]
extern "C" void kernel_launch(void* const* d_in, const int* in_sizes, int n_in,
                              void* d_out, int out_size) {
    const float* data = (const float*)d_in[0];
    const float* beta = (const float*)d_in[3];
    const float* z0   = (const float*)d_in[4];
    const float* v0   = (const float*)d_in[5];
    float* out = (float*)d_out;

    prep_kernel<<<1, 1024>>>(data, z0, v0);
    main_kernel<<<MAIN_BLOCKS, MAIN_THREADS>>>(data, beta, out);
}

// round 10
// speedup vs baseline: 1.9290x; 1.0858x over previous
#include <cuda_runtime.h>
#include <math.h>

#define N_POINTS 128
#define STEPS    50
#define N_EVENTS 10000
#define DT       2.0f
#define SQRT_PI_F 1.7724539f
#define PAD_S    52                                       // padded step stride
#define N_GROUPS 25                                       // 25 groups of 2 steps = 50 exact

#define N_PAIRS      ((N_POINTS * (N_POINTS - 1)) / 2)    // 8128
#define PAIR_THREADS (N_PAIRS * N_GROUPS)                 // 203200
#define MAIN_THREADS 256
#define MAIN_BLOCKS  ((PAIR_THREADS + N_EVENTS + MAIN_THREADS - 1) / MAIN_THREADS)  // 833

// ---- device scratch (allocation-free contract) ----
__device__ __align__(16) float  g_Zx[N_POINTS * PAD_S];
__device__ __align__(16) float  g_Zy[N_POINTS * PAD_S];
__device__ __align__(16) float  g_Vx[N_POINTS * PAD_S];
__device__ __align__(16) float  g_Vy[N_POINTS * PAD_S];
__device__ __align__(16) float2 g_tstf[PAD_S];            // (ts', tf'); tf'==ts' when invalid
__device__ unsigned char g_rowi[N_PAIRS];                 // pair -> row i LUT
__device__ double        g_acc   = 0.0;
__device__ unsigned int  g_count = 0;

__device__ __forceinline__ int tri_base(int i) {          // # pairs before row i
    return i * (N_POINTS - 1) - (i * (i - 1)) / 2;
}

// Abramowitz-Stegun 7.1.26: |err| < 1.5e-7
__device__ __forceinline__ float fast_erff(float x) {
    float ax = fabsf(x);
    float t  = __fdividef(1.0f, fmaf(0.3275911f, ax, 1.0f));
    float poly = t * fmaf(t, fmaf(t, fmaf(t, fmaf(t, 1.061405429f,
                    -1.453152027f), 1.421413741f), -0.284496736f), 0.254829592f);
    float r = 1.0f - poly * __expf(-ax * ax);
    return copysignf(r, x);
}

// ---------------------------------------------------------------------------
// Kernel A: 2 independent blocks x 1024.
//   block 0: event-time boundary scan -> ts/tf table (shared combine)
//   block 1: Z cumsum + V copy into padded SoA + pair-row LUT
// ---------------------------------------------------------------------------
__global__ void __launch_bounds__(1024)
prep_kernel(const float* __restrict__ data,
            const float* __restrict__ z0,
            const float* __restrict__ v0) {
    const int tid = threadIdx.x;

    if (blockIdx.x == 0) {
        __shared__ float sTs[STEPS + 1];
        __shared__ float sVl[STEPS];
        const float denom = DT + DT * 0.001f;             // 2.002f, matches ref rounding
        const float tlast = __ldg(&data[(N_EVENTS - 1) * 3 + 2]);
        if (tid <= STEPS) {
            sTs[tid] = tlast;                             // empty segment -> times[M-1]
            if (tid < STEPS) sVl[tid] = 0.0f;
        }
        __syncthreads();
        for (int m = tid; m < N_EVENTS; m += 1024) {      // 10 iters, independent loads
            float t   = data[m * 3 + 2];
            int   idx = (int)floorf(t / denom);
            int newseg = (m == 0) ||
                         (((int)floorf(data[m * 3 - 1] / denom)) != idx);
            if (newseg) { sTs[idx] = t; sVl[idx] = 1.0f; }
        }
        __syncthreads();
        if (tid < STEPS) {
            float tsA = sTs[tid];
            float tfA = (sVl[tid] != 0.0f) ? sTs[tid + 1] : tsA;  // invalid -> term 0
            g_tstf[tid] = make_float2(tsA, tfA);
        } else if (tid < PAD_S) {
            g_tstf[tid] = make_float2(0.0f, 0.0f);
        }
    } else {
        // Z cumsum into padded SoA: one (point,dim) row per thread
        if (tid < 2 * N_POINTS) {
            int p = tid >> 1, d = tid & 1;
            float* Zr = (d ? g_Zy : g_Zx) + p * PAD_S;
            float* Vr = (d ? g_Vy : g_Vx) + p * PAD_S;
            const float* vr = v0 + tid * STEPS;           // v0 row = p*2 + d
            float z = __ldg(&z0[tid]);
            Zr[0] = z;                                    // Z_steps[0] = z0
            float cum = 0.0f;
            #pragma unroll
            for (int s = 1; s < STEPS; ++s) {
                cum += z + vr[s - 1] * DT;                // same fp order as reference
                Zr[s] = cum;
            }
            Zr[50] = 0.0f; Zr[51] = 0.0f;
            Vr[50] = 0.0f; Vr[51] = 0.0f;
        }
        // V copy into padded SoA
        for (int idx = tid; idx < 2 * N_POINTS * STEPS; idx += 1024) {
            int row = idx / STEPS, s = idx - row * STEPS;
            int p = row >> 1, d = row & 1;
            ((d ? g_Vy : g_Vx) + p * PAD_S)[s] = v0[idx];
        }
        // pair -> row LUT
        for (int p = tid; p < N_PAIRS; p += 1024) {
            float disc = (float)(255 * 255 - 8 * p);
            int i = (int)((255.0f - sqrtf(disc)) * 0.5f);
            i = min(max(i, 0), N_POINTS - 2);
            while (i < N_POINTS - 2 && tri_base(i + 1) <= p) ++i;
            while (i > 0 && tri_base(i) > p) --i;
            g_rowi[p] = (unsigned char)i;
        }
    }
}

// ---------------------------------------------------------------------------
// Kernel B: one (pair, 2-step group) per thread + event threads.
// ---------------------------------------------------------------------------
union F4 { float4 v; float a[4]; };

__global__ void __launch_bounds__(MAIN_THREADS)
main_kernel(const float* __restrict__ data,
            const float* __restrict__ beta,
            float* __restrict__ out) {
    const int   gid = blockIdx.x * MAIN_THREADS + threadIdx.x;
    const float b0  = __ldg(&beta[0]);
    float facc = 0.0f;

    if (gid < PAIR_THREADS) {
        int p  = gid / N_GROUPS;
        int s0 = (gid - p * N_GROUPS) * 2;
        int i  = (int)__ldg(&g_rowi[p]);
        int j  = i + 1 + (p - tri_base(i));

        const int oi = i * PAD_S + s0, oj = j * PAD_S + s0;
        float2 zxi = __ldg((const float2*)(g_Zx + oi));
        float2 zyi = __ldg((const float2*)(g_Zy + oi));
        float2 zxj = __ldg((const float2*)(g_Zx + oj));
        float2 zyj = __ldg((const float2*)(g_Zy + oj));
        float2 vxi = __ldg((const float2*)(g_Vx + oi));
        float2 vyi = __ldg((const float2*)(g_Vy + oi));
        float2 vxj = __ldg((const float2*)(g_Vx + oj));
        float2 vyj = __ldg((const float2*)(g_Vy + oj));
        F4 tt; tt.v = __ldg((const float4*)(&g_tstf[s0]));    // (ts0,tf0,ts1,tf1)

        #pragma unroll
        for (int k = 0; k < 2; ++k) {
            float dzx = (k ? zxi.y : zxi.x) - (k ? zxj.y : zxj.x);
            float dzy = (k ? zyi.y : zyi.x) - (k ? zyj.y : zyj.x);
            float dvx = (k ? vxi.y : vxi.x) - (k ? vxj.y : vxj.x);
            float dvy = (k ? vyi.y : vyi.x) - (k ? vyj.y : vyj.x);

            float a = fmaxf(dvx * dvx + dvy * dvy, 1e-10f);
            float b = 2.0f * (dzx * dvx + dzy * dvy);
            float c = dzx * dzx + dzy * dzy;
            float rsa    = rsqrtf(a);
            float inv2sa = 0.5f * rsa;
            float shift  = b * inv2sa;
            float arg    = b0 - c + shift * shift;
            if (arg > -25.0f) {                           // exp-underflow skip
                float sa  = a * rsa;
                float ts  = tt.a[2 * k];
                float tf  = tt.a[2 * k + 1];
                float loa = fmaf(sa, ts, shift);
                float hia = fmaf(sa, tf, shift);
                if (loa < 5.0f && hia > -5.0f) {          // erf-saturation skip
                    float pref = SQRT_PI_F * inv2sa * __expf(arg);
                    facc -= pref * (fast_erff(hia) - fast_erff(loa));
                }
            }
        }
    } else if (gid - PAIR_THREADS < N_EVENTS) {
        int e = gid - PAIR_THREADS;
        const float denom = DT + DT * 0.001f;
        float si = __ldg(&data[e * 3]);
        float dj = __ldg(&data[e * 3 + 1]);
        float t  = __ldg(&data[e * 3 + 2]);
        int ii = (int)si, jj = (int)dj;
        float stepf = floorf(t / denom);
        int   id    = (int)stepf;
        float delta = t - stepf * DT;
        int oi = ii * PAD_S + id, oj = jj * PAD_S + id;
        float dx = (__ldg(&g_Zx[oi]) + __ldg(&g_Vx[oi]) * delta)
                 - (__ldg(&g_Zx[oj]) + __ldg(&g_Vx[oj]) * delta);
        float dy = (__ldg(&g_Zy[oi]) + __ldg(&g_Vy[oi]) * delta)
                 - (__ldg(&g_Zy[oj]) + __ldg(&g_Vy[oj]) * delta);
        facc += b0 - (dx * dx + dy * dy);
    }

    // ---- reduction: warp shuffle (double) -> smem -> warp0 -> global atomic ----
    __shared__ double sRd[MAIN_THREADS / 32];
    double v = (double)facc;
    #pragma unroll
    for (int off = 16; off > 0; off >>= 1)
        v += __shfl_down_sync(0xffffffffu, v, off);
    int warp = threadIdx.x >> 5, lane = threadIdx.x & 31;
    if (lane == 0) sRd[warp] = v;
    __syncthreads();
    if (warp == 0) {
        v = (lane < MAIN_THREADS / 32) ? sRd[lane] : 0.0;
        #pragma unroll
        for (int off = 4; off > 0; off >>= 1)
            v += __shfl_down_sync(0xffffffffu, v, off);
        if (lane == 0) {
            atomicAdd(&g_acc, v);
            __threadfence();
            unsigned int old = atomicAdd(&g_count, 1u);
            if (old == gridDim.x - 1) {                   // last block: write + reset
                double total = atomicAdd(&g_acc, 0.0);
                out[0] = (float)total;
                g_acc   = 0.0;
                g_count = 0u;
            }
        }
    }
}

// Inputs (metadata order): data[30000], t0[1], tn[1], beta[1], z0[256], v0[12800]
extern "C" void kernel_launch(void* const* d_in, const int* in_sizes, int n_in,
                              void* d_out, int out_size) {
    const float* data = (const float*)d_in[0];
    const float* beta = (const float*)d_in[3];
    const float* z0   = (const float*)d_in[4];
    const float* v0   = (const float*)d_in[5];
    float* out = (float*)d_out;

    prep_kernel<<<2, 1024>>>(data, z0, v0);
    main_kernel<<<MAIN_BLOCKS, MAIN_THREADS>>>(data, beta, out);
}

// round 11
// speedup vs baseline: 1.9419x; 1.0066x over previous
#include <cuda_runtime.h>
#include <math.h>

#define N_POINTS 128
#define STEPS    50
#define N_EVENTS 10000
#define DT       2.0f
#define SQRT_PI_F 1.7724539f
#define PAD_S    52                                       // padded step stride
#define N_GROUPS 25                                       // 25 groups of 2 steps = 50 exact

#define N_PAIRS      ((N_POINTS * (N_POINTS - 1)) / 2)    // 8128
#define PAIR_THREADS (N_PAIRS * N_GROUPS)                 // 203200
#define MAIN_THREADS 256
#define MAIN_BLOCKS  ((PAIR_THREADS + N_EVENTS + MAIN_THREADS - 1) / MAIN_THREADS)  // 833

// ---- device scratch (allocation-free contract) ----
__device__ __align__(16) float  g_Zx[N_POINTS * PAD_S];
__device__ __align__(16) float  g_Zy[N_POINTS * PAD_S];
__device__ __align__(16) float  g_Vx[N_POINTS * PAD_S];
__device__ __align__(16) float  g_Vy[N_POINTS * PAD_S];
__device__ __align__(16) float2 g_tstf[PAD_S];            // (ts', tf'); tf'==ts' when invalid
__device__ unsigned char g_rowi[N_PAIRS];                 // pair -> row i LUT
__device__ double        g_acc   = 0.0;
__device__ unsigned int  g_count = 0;

__device__ __forceinline__ int tri_base(int i) {          // # pairs before row i
    return i * (N_POINTS - 1) - (i * (i - 1)) / 2;
}

// Abramowitz-Stegun 7.1.26: |err| < 1.5e-7
__device__ __forceinline__ float fast_erff(float x) {
    float ax = fabsf(x);
    float t  = __fdividef(1.0f, fmaf(0.3275911f, ax, 1.0f));
    float poly = t * fmaf(t, fmaf(t, fmaf(t, fmaf(t, 1.061405429f,
                    -1.453152027f), 1.421413741f), -0.284496736f), 0.254829592f);
    float r = 1.0f - poly * __expf(-ax * ax);
    return copysignf(r, x);
}

// ---------------------------------------------------------------------------
// Kernel A: 2 independent blocks x 1024 (unchanged from R10) + PDL trigger.
// ---------------------------------------------------------------------------
__global__ void __launch_bounds__(1024)
prep_kernel(const float* __restrict__ data,
            const float* __restrict__ z0,
            const float* __restrict__ v0) {
    const int tid = threadIdx.x;

    if (blockIdx.x == 0) {
        __shared__ float sTs[STEPS + 1];
        __shared__ float sVl[STEPS];
        const float denom = DT + DT * 0.001f;             // 2.002f, matches ref rounding
        const float tlast = __ldg(&data[(N_EVENTS - 1) * 3 + 2]);
        if (tid <= STEPS) {
            sTs[tid] = tlast;                             // empty segment -> times[M-1]
            if (tid < STEPS) sVl[tid] = 0.0f;
        }
        __syncthreads();
        for (int m = tid; m < N_EVENTS; m += 1024) {      // 10 iters, independent loads
            float t   = data[m * 3 + 2];
            int   idx = (int)floorf(t / denom);
            int newseg = (m == 0) ||
                         (((int)floorf(data[m * 3 - 1] / denom)) != idx);
            if (newseg) { sTs[idx] = t; sVl[idx] = 1.0f; }
        }
        __syncthreads();
        if (tid < STEPS) {
            float tsA = sTs[tid];
            float tfA = (sVl[tid] != 0.0f) ? sTs[tid + 1] : tsA;  // invalid -> term 0
            g_tstf[tid] = make_float2(tsA, tfA);
        } else if (tid < PAD_S) {
            g_tstf[tid] = make_float2(0.0f, 0.0f);
        }
    } else {
        if (tid < 2 * N_POINTS) {                         // Z cumsum, one row/thread
            int p = tid >> 1, d = tid & 1;
            float* Zr = (d ? g_Zy : g_Zx) + p * PAD_S;
            float* Vr = (d ? g_Vy : g_Vx) + p * PAD_S;
            const float* vr = v0 + tid * STEPS;           // v0 row = p*2 + d
            float z = __ldg(&z0[tid]);
            Zr[0] = z;                                    // Z_steps[0] = z0
            float cum = 0.0f;
            #pragma unroll
            for (int s = 1; s < STEPS; ++s) {
                cum += z + vr[s - 1] * DT;                // same fp order as reference
                Zr[s] = cum;
            }
            Zr[50] = 0.0f; Zr[51] = 0.0f;
            Vr[50] = 0.0f; Vr[51] = 0.0f;
        }
        for (int idx = tid; idx < 2 * N_POINTS * STEPS; idx += 1024) {  // V copy
            int row = idx / STEPS, s = idx - row * STEPS;
            int p = row >> 1, d = row & 1;
            ((d ? g_Vy : g_Vx) + p * PAD_S)[s] = v0[idx];
        }
        for (int p = tid; p < N_PAIRS; p += 1024) {       // pair -> row LUT
            float disc = (float)(255 * 255 - 8 * p);
            int i = (int)((255.0f - sqrtf(disc)) * 0.5f);
            i = min(max(i, 0), N_POINTS - 2);
            while (i < N_POINTS - 2 && tri_base(i + 1) <= p) ++i;
            while (i > 0 && tri_base(i) > p) --i;
            g_rowi[p] = (unsigned char)i;
        }
    }
#if __CUDA_ARCH__ >= 900
    cudaTriggerProgrammaticLaunchCompletion();
#endif
}

// ---------------------------------------------------------------------------
// Kernel B: one (pair, 2-step group) per thread; MUFU-free skip tests.
// ---------------------------------------------------------------------------
union F4 { float4 v; float a[4]; };

__global__ void __launch_bounds__(MAIN_THREADS)
main_kernel(const float* __restrict__ data,
            const float* __restrict__ beta,
            float* __restrict__ out) {
    const int   gid = blockIdx.x * MAIN_THREADS + threadIdx.x;
    const float b0  = __ldg(&beta[0]);
#if __CUDA_ARCH__ >= 900
    cudaGridDependencySynchronize();                      // wait: prep tables visible
#endif
    float facc = 0.0f;

    if (gid < PAIR_THREADS) {
        int p  = gid / N_GROUPS;
        int s0 = (gid - p * N_GROUPS) * 2;
        int i  = (int)__ldg(&g_rowi[p]);
        int j  = i + 1 + (p - tri_base(i));

        const int oi = i * PAD_S + s0, oj = j * PAD_S + s0;
        float2 zxi = __ldg((const float2*)(g_Zx + oi));
        float2 zyi = __ldg((const float2*)(g_Zy + oi));
        float2 zxj = __ldg((const float2*)(g_Zx + oj));
        float2 zyj = __ldg((const float2*)(g_Zy + oj));
        float2 vxi = __ldg((const float2*)(g_Vx + oi));
        float2 vyi = __ldg((const float2*)(g_Vy + oi));
        float2 vxj = __ldg((const float2*)(g_Vx + oj));
        float2 vyj = __ldg((const float2*)(g_Vy + oj));
        F4 tt; tt.v = __ldg((const float4*)(&g_tstf[s0]));    // (ts0,tf0,ts1,tf1)

        #pragma unroll
        for (int k = 0; k < 2; ++k) {
            float dzx = (k ? zxi.y : zxi.x) - (k ? zxj.y : zxj.x);
            float dzy = (k ? zyi.y : zyi.x) - (k ? zyj.y : zyj.x);
            float dvx = (k ? vxi.y : vxi.x) - (k ? vxj.y : vxj.x);
            float dvy = (k ? vyi.y : vyi.x) - (k ? vyj.y : vyj.x);

            float a  = fmaxf(dvx * dvx + dvy * dvy, 1e-10f);
            float b  = 2.0f * (dzx * dvx + dzy * dvy);
            float c  = dzx * dzx + dzy * dzy;
            float bc = b0 - c;
            float ts = tt.a[2 * k];
            float tf = tt.a[2 * k + 1];

            // ---- MUFU-free skip tests ----
            // C1: arg = bc + b^2/4a > -25  <=>  4a(bc+25) + b^2 > 0
            // C2: loa < 5   <=>  u=2a*ts+b <= 0  or  u^2 < 100a
            // C3: hia > -5  <=>  v=2a*tf+b >= 0  or  v^2 < 100a
            float u = fmaf(2.0f * a, ts, b);
            float v = fmaf(2.0f * a, tf, b);
            bool live = (fmaf(4.0f * a, bc + 25.0f, b * b) > 0.0f)
                     && (u <= 0.0f || u * u < 100.0f * a)
                     && (v >= 0.0f || v * v < 100.0f * a);
            if (live) {
                float rsa    = rsqrtf(a);
                float inv2sa = 0.5f * rsa;
                float sa     = a * rsa;
                float shift  = b * inv2sa;
                float arg    = bc + shift * shift;
                float loa    = fmaf(sa, ts, shift);
                float hia    = fmaf(sa, tf, shift);
                float pref   = SQRT_PI_F * inv2sa * __expf(arg);
                facc -= pref * (fast_erff(hia) - fast_erff(loa));
            }
        }
    } else if (gid - PAIR_THREADS < N_EVENTS) {
        int e = gid - PAIR_THREADS;
        const float denom = DT + DT * 0.001f;
        float si = __ldg(&data[e * 3]);
        float dj = __ldg(&data[e * 3 + 1]);
        float t  = __ldg(&data[e * 3 + 2]);
        int ii = (int)si, jj = (int)dj;
        float stepf = floorf(t / denom);
        int   id    = (int)stepf;
        float delta = t - stepf * DT;
        int oi = ii * PAD_S + id, oj = jj * PAD_S + id;
        float dx = (__ldg(&g_Zx[oi]) + __ldg(&g_Vx[oi]) * delta)
                 - (__ldg(&g_Zx[oj]) + __ldg(&g_Vx[oj]) * delta);
        float dy = (__ldg(&g_Zy[oi]) + __ldg(&g_Vy[oi]) * delta)
                 - (__ldg(&g_Zy[oj]) + __ldg(&g_Vy[oj]) * delta);
        facc += b0 - (dx * dx + dy * dy);
    }

    // ---- reduction: warp shuffle (double) -> smem -> warp0 -> global atomic ----
    __shared__ double sRd[MAIN_THREADS / 32];
    double v = (double)facc;
    #pragma unroll
    for (int off = 16; off > 0; off >>= 1)
        v += __shfl_down_sync(0xffffffffu, v, off);
    int warp = threadIdx.x >> 5, lane = threadIdx.x & 31;
    if (lane == 0) sRd[warp] = v;
    __syncthreads();
    if (warp == 0) {
        v = (lane < MAIN_THREADS / 32) ? sRd[lane] : 0.0;
        #pragma unroll
        for (int off = 4; off > 0; off >>= 1)
            v += __shfl_down_sync(0xffffffffu, v, off);
        if (lane == 0) {
            atomicAdd(&g_acc, v);
            __threadfence();
            unsigned int old = atomicAdd(&g_count, 1u);
            if (old == gridDim.x - 1) {                   // last block: write + reset
                double total = atomicAdd(&g_acc, 0.0);
                out[0] = (float)total;
                g_acc   = 0.0;
                g_count = 0u;
            }
        }
    }
}

// Inputs (metadata order): data[30000], t0[1], tn[1], beta[1], z0[256], v0[12800]
extern "C" void kernel_launch(void* const* d_in, const int* in_sizes, int n_in,
                              void* d_out, int out_size) {
    const float* data = (const float*)d_in[0];
    const float* beta = (const float*)d_in[3];
    const float* z0   = (const float*)d_in[4];
    const float* v0   = (const float*)d_in[5];
    float* out = (float*)d_out;

    prep_kernel<<<2, 1024>>>(data, z0, v0);

    // PDL: overlap main's launch/dispatch with prep's execution
    cudaLaunchConfig_t cfg = {};
    cfg.gridDim  = dim3(MAIN_BLOCKS, 1, 1);
    cfg.blockDim = dim3(MAIN_THREADS, 1, 1);
    cfg.stream   = 0;
    cudaLaunchAttribute attr[1];
    attr[0].id = cudaLaunchAttributeProgrammaticStreamSerialization;
    attr[0].val.programmaticStreamSerializationAllowed = 1;
    cfg.attrs    = attr;
    cfg.numAttrs = 1;
    cudaLaunchKernelEx(&cfg, main_kernel, data, beta, out);
}

// round 12
// speedup vs baseline: 2.4715x; 1.2727x over previous
#include <cuda_runtime.h>
#include <math.h>

#define N_POINTS 128
#define STEPS    50
#define N_EVENTS 10000
#define DT       2.0f
#define SQRT_PI_F 1.7724539f
#define PAD_S    52                                       // padded step stride
#define N_GROUPS 25                                       // 25 groups of 2 steps = 50 exact

#define N_PAIRS      ((N_POINTS * (N_POINTS - 1)) / 2)    // 8128
#define PAIR_THREADS (N_PAIRS * N_GROUPS)                 // 203200
#define MAIN_THREADS 256
#define MAIN_BLOCKS  ((PAIR_THREADS + N_EVENTS + MAIN_THREADS - 1) / MAIN_THREADS)  // 833

// ---- device scratch (allocation-free contract) ----
__device__ __align__(16) float  g_Zx[N_POINTS * PAD_S];
__device__ __align__(16) float  g_Zy[N_POINTS * PAD_S];
__device__ __align__(16) float  g_Vx[N_POINTS * PAD_S];
__device__ __align__(16) float  g_Vy[N_POINTS * PAD_S];
__device__ __align__(16) float2 g_tstf[PAD_S];            // (ts', tf'); tf'==ts' when invalid
__device__ unsigned char g_rowi[N_PAIRS];                 // pair -> row i LUT
__device__ double        g_acc   = 0.0;
__device__ unsigned int  g_count = 0;

__device__ __forceinline__ int tri_base(int i) {          // # pairs before row i
    return i * (N_POINTS - 1) - (i * (i - 1)) / 2;
}

// Abramowitz-Stegun 7.1.26: |err| < 1.5e-7
__device__ __forceinline__ float fast_erff(float x) {
    float ax = fabsf(x);
    float t  = __fdividef(1.0f, fmaf(0.3275911f, ax, 1.0f));
    float poly = t * fmaf(t, fmaf(t, fmaf(t, fmaf(t, 1.061405429f,
                    -1.453152027f), 1.421413741f), -0.284496736f), 0.254829592f);
    float r = 1.0f - poly * __expf(-ax * ax);
    return copysignf(r, x);
}

// ---------------------------------------------------------------------------
// Kernel A: 4 independent blocks x 1024 — each latency chain on its own SM.
//   b0: event-time boundary scan -> ts/tf table
//   b1: Z cumsum (+pads)   b2: V copy   b3: pair-row LUT
// ---------------------------------------------------------------------------
__global__ void __launch_bounds__(1024)
prep_kernel(const float* __restrict__ data,
            const float* __restrict__ z0,
            const float* __restrict__ v0) {
    const int tid = threadIdx.x;
    const int blk = blockIdx.x;

    if (blk == 0) {
        __shared__ float sTs[STEPS + 1];
        __shared__ float sVl[STEPS];
        const float denom = DT + DT * 0.001f;             // 2.002f, matches ref rounding
        const float tlast = __ldg(&data[(N_EVENTS - 1) * 3 + 2]);
        if (tid <= STEPS) {
            sTs[tid] = tlast;                             // empty segment -> times[M-1]
            if (tid < STEPS) sVl[tid] = 0.0f;
        }
        __syncthreads();
        for (int m = tid; m < N_EVENTS; m += 1024) {      // 10 iters, independent loads
            float t   = data[m * 3 + 2];
            int   idx = (int)floorf(t / denom);
            int newseg = (m == 0) ||
                         (((int)floorf(data[m * 3 - 1] / denom)) != idx);
            if (newseg) { sTs[idx] = t; sVl[idx] = 1.0f; }
        }
        __syncthreads();
        if (tid < STEPS) {
            float tsA = sTs[tid];
            float tfA = (sVl[tid] != 0.0f) ? sTs[tid + 1] : tsA;  // invalid -> term 0
            g_tstf[tid] = make_float2(tsA, tfA);
        } else if (tid < PAD_S) {
            g_tstf[tid] = make_float2(0.0f, 0.0f);
        }
    } else if (blk == 1) {
        if (tid < 2 * N_POINTS) {                         // Z cumsum, one row/thread
            int p = tid >> 1, d = tid & 1;
            float* Zr = (d ? g_Zy : g_Zx) + p * PAD_S;
            float* Vr = (d ? g_Vy : g_Vx) + p * PAD_S;
            const float* vr = v0 + tid * STEPS;           // v0 row = p*2 + d
            float z = __ldg(&z0[tid]);
            Zr[0] = z;                                    // Z_steps[0] = z0
            float cum = 0.0f;
            #pragma unroll
            for (int s = 1; s < STEPS; ++s) {
                cum += z + vr[s - 1] * DT;                // same fp order as reference
                Zr[s] = cum;
            }
            Zr[50] = 0.0f; Zr[51] = 0.0f;
            Vr[50] = 0.0f; Vr[51] = 0.0f;
        }
    } else if (blk == 2) {
        for (int idx = tid; idx < 2 * N_POINTS * STEPS; idx += 1024) {  // V copy
            int row = idx / STEPS, s = idx - row * STEPS;
            int p = row >> 1, d = row & 1;
            ((d ? g_Vy : g_Vx) + p * PAD_S)[s] = v0[idx];
        }
    } else {
        for (int p = tid; p < N_PAIRS; p += 1024) {       // pair -> row LUT
            float disc = (float)(255 * 255 - 8 * p);
            int i = (int)((255.0f - sqrtf(disc)) * 0.5f);
            i = min(max(i, 0), N_POINTS - 2);
            while (i < N_POINTS - 2 && tri_base(i + 1) <= p) ++i;
            while (i > 0 && tri_base(i) > p) --i;
            g_rowi[p] = (unsigned char)i;
        }
    }
#if __CUDA_ARCH__ >= 900
    cudaTriggerProgrammaticLaunchCompletion();
#endif
}

// ---------------------------------------------------------------------------
// Kernel B: one (pair, 2-step group) per thread; FLOAT warp reduction.
// ---------------------------------------------------------------------------
union F4 { float4 v; float a[4]; };

__global__ void __launch_bounds__(MAIN_THREADS)
main_kernel(const float* __restrict__ data,
            const float* __restrict__ beta,
            float* __restrict__ out) {
    const int   gid = blockIdx.x * MAIN_THREADS + threadIdx.x;
    const float b0  = __ldg(&beta[0]);
#if __CUDA_ARCH__ >= 900
    cudaGridDependencySynchronize();                      // wait: prep tables visible
#endif
    float facc = 0.0f;

    if (gid < PAIR_THREADS) {
        int p  = gid / N_GROUPS;
        int s0 = (gid - p * N_GROUPS) * 2;
        int i  = (int)__ldg(&g_rowi[p]);
        int j  = i + 1 + (p - tri_base(i));

        const int oi = i * PAD_S + s0, oj = j * PAD_S + s0;
        float2 zxi = __ldg((const float2*)(g_Zx + oi));
        float2 zyi = __ldg((const float2*)(g_Zy + oi));
        float2 zxj = __ldg((const float2*)(g_Zx + oj));
        float2 zyj = __ldg((const float2*)(g_Zy + oj));
        float2 vxi = __ldg((const float2*)(g_Vx + oi));
        float2 vyi = __ldg((const float2*)(g_Vy + oi));
        float2 vxj = __ldg((const float2*)(g_Vx + oj));
        float2 vyj = __ldg((const float2*)(g_Vy + oj));
        F4 tt; tt.v = __ldg((const float4*)(&g_tstf[s0]));    // (ts0,tf0,ts1,tf1)

        #pragma unroll
        for (int k = 0; k < 2; ++k) {
            float dzx = (k ? zxi.y : zxi.x) - (k ? zxj.y : zxj.x);
            float dzy = (k ? zyi.y : zyi.x) - (k ? zyj.y : zyj.x);
            float dvx = (k ? vxi.y : vxi.x) - (k ? vxj.y : vxj.x);
            float dvy = (k ? vyi.y : vyi.x) - (k ? vyj.y : vyj.x);

            float a  = fmaxf(dvx * dvx + dvy * dvy, 1e-10f);
            float b  = 2.0f * (dzx * dvx + dzy * dvy);
            float c  = dzx * dzx + dzy * dzy;
            float bc = b0 - c;
            float ts = tt.a[2 * k];
            float tf = tt.a[2 * k + 1];

            // MUFU-free skip tests (exact algebra, see R11)
            float u = fmaf(2.0f * a, ts, b);
            float v = fmaf(2.0f * a, tf, b);
            bool live = (fmaf(4.0f * a, bc + 25.0f, b * b) > 0.0f)
                     && (u <= 0.0f || u * u < 100.0f * a)
                     && (v >= 0.0f || v * v < 100.0f * a);
            if (live) {
                float rsa    = rsqrtf(a);
                float inv2sa = 0.5f * rsa;
                float sa     = a * rsa;
                float shift  = b * inv2sa;
                float arg    = bc + shift * shift;
                float loa    = fmaf(sa, ts, shift);
                float hia    = fmaf(sa, tf, shift);
                float pref   = SQRT_PI_F * inv2sa * __expf(arg);
                facc -= pref * (fast_erff(hia) - fast_erff(loa));
            }
        }
    } else if (gid - PAIR_THREADS < N_EVENTS) {
        int e = gid - PAIR_THREADS;
        const float denom = DT + DT * 0.001f;
        float si = __ldg(&data[e * 3]);
        float dj = __ldg(&data[e * 3 + 1]);
        float t  = __ldg(&data[e * 3 + 2]);
        int ii = (int)si, jj = (int)dj;
        float stepf = floorf(t / denom);
        int   id    = (int)stepf;
        float delta = t - stepf * DT;
        int oi = ii * PAD_S + id, oj = jj * PAD_S + id;
        float dx = (__ldg(&g_Zx[oi]) + __ldg(&g_Vx[oi]) * delta)
                 - (__ldg(&g_Zx[oj]) + __ldg(&g_Vx[oj]) * delta);
        float dy = (__ldg(&g_Zy[oi]) + __ldg(&g_Vy[oi]) * delta)
                 - (__ldg(&g_Zy[oj]) + __ldg(&g_Vy[oj]) * delta);
        facc += b0 - (dx * dx + dy * dy);
    }

    // ---- reduction: FLOAT warp shuffle -> double smem -> warp0 -> atomic ----
    __shared__ double sRd[MAIN_THREADS / 32];
    float fv = facc;
    #pragma unroll
    for (int off = 16; off > 0; off >>= 1)                // FP32 pipe, not FP64
        fv += __shfl_down_sync(0xffffffffu, fv, off);
    int warp = threadIdx.x >> 5, lane = threadIdx.x & 31;
    if (lane == 0) sRd[warp] = (double)fv;                // promote once per warp
    __syncthreads();
    if (warp == 0) {
        double v = (lane < MAIN_THREADS / 32) ? sRd[lane] : 0.0;
        #pragma unroll
        for (int off = 4; off > 0; off >>= 1)             // 3 DADD levels, warp0 only
            v += __shfl_down_sync(0xffffffffu, v, off);
        if (lane == 0) {
            atomicAdd(&g_acc, v);
            __threadfence();
            unsigned int old = atomicAdd(&g_count, 1u);
            if (old == gridDim.x - 1) {                   // last block: write + reset
                double total = atomicAdd(&g_acc, 0.0);
                out[0] = (float)total;
                g_acc   = 0.0;
                g_count = 0u;
            }
        }
    }
}

// Inputs (metadata order): data[30000], t0[1], tn[1], beta[1], z0[256], v0[12800]
extern "C" void kernel_launch(void* const* d_in, const int* in_sizes, int n_in,
                              void* d_out, int out_size) {
    const float* data = (const float*)d_in[0];
    const float* beta = (const float*)d_in[3];
    const float* z0   = (const float*)d_in[4];
    const float* v0   = (const float*)d_in[5];
    float* out = (float*)d_out;

    prep_kernel<<<4, 1024>>>(data, z0, v0);

    // PDL: overlap main's launch/dispatch with prep's execution
    cudaLaunchConfig_t cfg = {};
    cfg.gridDim  = dim3(MAIN_BLOCKS, 1, 1);
    cfg.blockDim = dim3(MAIN_THREADS, 1, 1);
    cfg.stream   = 0;
    cudaLaunchAttribute attr[1];
    attr[0].id = cudaLaunchAttributeProgrammaticStreamSerialization;
    attr[0].val.programmaticStreamSerializationAllowed = 1;
    cfg.attrs    = attr;
    cfg.numAttrs = 1;
    cudaLaunchKernelEx(&cfg, main_kernel, data, beta, out);
}

// round 15
// speedup vs baseline: 2.5636x; 1.0373x over previous
#include <cuda_runtime.h>
#include <math.h>

#define N_POINTS 128
#define STEPS    50
#define N_EVENTS 10000
#define DT       2.0f
#define SQRT_PI_F 1.7724539f
#define PAD_S    52                                       // padded step stride
#define N_GROUPS 25                                       // 25 groups of 2 steps = 50 exact

#define N_PAIRS      ((N_POINTS * (N_POINTS - 1)) / 2)    // 8128
#define PAIR_THREADS (N_PAIRS * N_GROUPS)                 // 203200
#define MAIN_THREADS 256
#define MAIN_BLOCKS  ((PAIR_THREADS + N_EVENTS + MAIN_THREADS - 1) / MAIN_THREADS)  // 833

// ---- device scratch (allocation-free contract) ----
__device__ __align__(16) float  g_Zx[N_POINTS * PAD_S];
__device__ __align__(16) float  g_Zy[N_POINTS * PAD_S];
__device__ __align__(16) float  g_Vx[N_POINTS * PAD_S];
__device__ __align__(16) float  g_Vy[N_POINTS * PAD_S];
__device__ __align__(16) float2 g_tstf[PAD_S];            // (ts', tf'); tf'==ts' when invalid
__device__ unsigned char g_rowi[N_PAIRS];                 // pair -> row i LUT
__device__ double        g_acc   = 0.0;
__device__ unsigned int  g_count = 0;

__device__ __forceinline__ int tri_base(int i) {          // # pairs before row i
    return i * (N_POINTS - 1) - (i * (i - 1)) / 2;
}

// Abramowitz-Stegun 7.1.28: erf(x) = 1 - (1 + a1 x + ... + a6 x^6)^-16,
// |err| <= 3e-7. NO exp — single MUFU reciprocal via __fdividef.
// Overflow-safe: p^16 -> inf  =>  1/inf -> 0  =>  erf -> 1.
__device__ __forceinline__ float fast_erf28(float x) {
    const float a1 = 0.0705230784f, a2 = 0.0422820123f, a3 = 0.0092705272f,
                a4 = 0.0001520143f, a5 = 0.0002765672f, a6 = 0.0000430638f;
    float ax = fabsf(x);
    float p = fmaf(ax, a6, a5);
    p = fmaf(ax, p, a4);
    p = fmaf(ax, p, a3);
    p = fmaf(ax, p, a2);
    p = fmaf(ax, p, a1);
    p = fmaf(ax, p, 1.0f);
    float p2  = p  * p;
    float p4  = p2 * p2;
    float p8  = p4 * p4;
    float p16 = p8 * p8;
    float r   = __fdividef(1.0f, p16);                    // MUFU.RCP + FMUL
    return copysignf(1.0f - r, x);
}

// ---------------------------------------------------------------------------
// Kernel A: 4 independent blocks x 1024 — each latency chain on its own SM.
//   b0: event-time boundary scan -> ts/tf table
//   b1: Z cumsum (+pads)   b2: V copy   b3: pair-row LUT
// ---------------------------------------------------------------------------
__global__ void __launch_bounds__(1024)
prep_kernel(const float* __restrict__ data,
            const float* __restrict__ z0,
            const float* __restrict__ v0) {
    const int tid = threadIdx.x;
    const int blk = blockIdx.x;

    if (blk == 0) {
        __shared__ float sTs[STEPS + 1];
        __shared__ float sVl[STEPS];
        const float denom = DT + DT * 0.001f;             // 2.002f, matches ref rounding
        const float tlast = __ldg(&data[(N_EVENTS - 1) * 3 + 2]);
        if (tid <= STEPS) {
            sTs[tid] = tlast;                             // empty segment -> times[M-1]
            if (tid < STEPS) sVl[tid] = 0.0f;
        }
        __syncthreads();
        for (int m = tid; m < N_EVENTS; m += 1024) {      // 10 iters, independent loads
            float t   = data[m * 3 + 2];
            int   idx = (int)floorf(t / denom);
            int newseg = (m == 0) ||
                         (((int)floorf(data[m * 3 - 1] / denom)) != idx);
            if (newseg) { sTs[idx] = t; sVl[idx] = 1.0f; }
        }
        __syncthreads();
        if (tid < STEPS) {
            float tsA = sTs[tid];
            float tfA = (sVl[tid] != 0.0f) ? sTs[tid + 1] : tsA;  // invalid -> term 0
            g_tstf[tid] = make_float2(tsA, tfA);
        } else if (tid < PAD_S) {
            g_tstf[tid] = make_float2(0.0f, 0.0f);
        }
    } else if (blk == 1) {
        if (tid < 2 * N_POINTS) {                         // Z cumsum, one row/thread
            int p = tid >> 1, d = tid & 1;
            float* Zr = (d ? g_Zy : g_Zx) + p * PAD_S;
            float* Vr = (d ? g_Vy : g_Vx) + p * PAD_S;
            const float* vr = v0 + tid * STEPS;           // v0 row = p*2 + d
            float z = __ldg(&z0[tid]);
            Zr[0] = z;                                    // Z_steps[0] = z0
            float cum = 0.0f;
            #pragma unroll
            for (int s = 1; s < STEPS; ++s) {
                cum += z + vr[s - 1] * DT;                // same fp order as reference
                Zr[s] = cum;
            }
            Zr[50] = 0.0f; Zr[51] = 0.0f;
            Vr[50] = 0.0f; Vr[51] = 0.0f;
        }
    } else if (blk == 2) {
        for (int idx = tid; idx < 2 * N_POINTS * STEPS; idx += 1024) {  // V copy
            int row = idx / STEPS, s = idx - row * STEPS;
            int p = row >> 1, d = row & 1;
            ((d ? g_Vy : g_Vx) + p * PAD_S)[s] = v0[idx];
        }
    } else {
        for (int p = tid; p < N_PAIRS; p += 1024) {       // pair -> row LUT
            float disc = (float)(255 * 255 - 8 * p);
            int i = (int)((255.0f - sqrtf(disc)) * 0.5f);
            i = min(max(i, 0), N_POINTS - 2);
            while (i < N_POINTS - 2 && tri_base(i + 1) <= p) ++i;
            while (i > 0 && tri_base(i) > p) --i;
            g_rowi[p] = (unsigned char)i;
        }
    }
#if __CUDA_ARCH__ >= 900
    cudaTriggerProgrammaticLaunchCompletion();
#endif
}

// ---------------------------------------------------------------------------
// Kernel B: one (pair, 2-step group) per thread; exp-free erf (4 MUFU/term).
// ---------------------------------------------------------------------------
union F4 { float4 v; float a[4]; };

__global__ void __launch_bounds__(MAIN_THREADS)
main_kernel(const float* __restrict__ data,
            const float* __restrict__ beta,
            float* __restrict__ out) {
    const int   gid = blockIdx.x * MAIN_THREADS + threadIdx.x;
    const float b0  = __ldg(&beta[0]);
#if __CUDA_ARCH__ >= 900
    cudaGridDependencySynchronize();                      // wait: prep tables visible
#endif
    float facc = 0.0f;

    if (gid < PAIR_THREADS) {
        int p  = gid / N_GROUPS;
        int s0 = (gid - p * N_GROUPS) * 2;
        int i  = (int)__ldg(&g_rowi[p]);
        int j  = i + 1 + (p - tri_base(i));

        const int oi = i * PAD_S + s0, oj = j * PAD_S + s0;
        float2 zxi = __ldg((const float2*)(g_Zx + oi));
        float2 zyi = __ldg((const float2*)(g_Zy + oi));
        float2 zxj = __ldg((const float2*)(g_Zx + oj));
        float2 zyj = __ldg((const float2*)(g_Zy + oj));
        float2 vxi = __ldg((const float2*)(g_Vx + oi));
        float2 vyi = __ldg((const float2*)(g_Vy + oi));
        float2 vxj = __ldg((const float2*)(g_Vx + oj));
        float2 vyj = __ldg((const float2*)(g_Vy + oj));
        F4 tt; tt.v = __ldg((const float4*)(&g_tstf[s0]));    // (ts0,tf0,ts1,tf1)

        #pragma unroll
        for (int k = 0; k < 2; ++k) {
            float dzx = (k ? zxi.y : zxi.x) - (k ? zxj.y : zxj.x);
            float dzy = (k ? zyi.y : zyi.x) - (k ? zyj.y : zyj.x);
            float dvx = (k ? vxi.y : vxi.x) - (k ? vxj.y : vxj.x);
            float dvy = (k ? vyi.y : vyi.x) - (k ? vyj.y : vyj.x);

            float a  = fmaxf(dvx * dvx + dvy * dvy, 1e-10f);
            float b  = 2.0f * (dzx * dvx + dzy * dvy);
            float c  = dzx * dzx + dzy * dzy;
            float bc = b0 - c;
            float ts = tt.a[2 * k];
            float tf = tt.a[2 * k + 1];

            // MUFU-free skip tests (exact algebra, see R11)
            float u = fmaf(2.0f * a, ts, b);
            float v = fmaf(2.0f * a, tf, b);
            bool live = (fmaf(4.0f * a, bc + 25.0f, b * b) > 0.0f)
                     && (u <= 0.0f || u * u < 100.0f * a)
                     && (v >= 0.0f || v * v < 100.0f * a);
            if (live) {
                float rsa    = rsqrtf(a);
                float inv2sa = 0.5f * rsa;
                float sa     = a * rsa;
                float shift  = b * inv2sa;
                float arg    = bc + shift * shift;
                float loa    = fmaf(sa, ts, shift);
                float hia    = fmaf(sa, tf, shift);
                float pref   = SQRT_PI_F * inv2sa * __expf(arg);
                facc -= pref * (fast_erf28(hia) - fast_erf28(loa));
            }
        }
    } else if (gid - PAIR_THREADS < N_EVENTS) {
        int e = gid - PAIR_THREADS;
        const float denom = DT + DT * 0.001f;
        float si = __ldg(&data[e * 3]);
        float dj = __ldg(&data[e * 3 + 1]);
        float t  = __ldg(&data[e * 3 + 2]);
        int ii = (int)si, jj = (int)dj;
        float stepf = floorf(t / denom);
        int   id    = (int)stepf;
        float delta = t - stepf * DT;
        int oi = ii * PAD_S + id, oj = jj * PAD_S + id;
        float dx = (__ldg(&g_Zx[oi]) + __ldg(&g_Vx[oi]) * delta)
                 - (__ldg(&g_Zx[oj]) + __ldg(&g_Vx[oj]) * delta);
        float dy = (__ldg(&g_Zy[oi]) + __ldg(&g_Vy[oi]) * delta)
                 - (__ldg(&g_Zy[oj]) + __ldg(&g_Vy[oj]) * delta);
        facc += b0 - (dx * dx + dy * dy);
    }

    // ---- reduction: FLOAT warp shuffle -> double smem -> warp0 -> atomic ----
    __shared__ double sRd[MAIN_THREADS / 32];
    float fv = facc;
    #pragma unroll
    for (int off = 16; off > 0; off >>= 1)                // FP32 pipe
        fv += __shfl_down_sync(0xffffffffu, fv, off);
    int warp = threadIdx.x >> 5, lane = threadIdx.x & 31;
    if (lane == 0) sRd[warp] = (double)fv;                // promote once per warp
    __syncthreads();
    if (warp == 0) {
        double v = (lane < MAIN_THREADS / 32) ? sRd[lane] : 0.0;
        #pragma unroll
        for (int off = 4; off > 0; off >>= 1)             // 3 DADD levels, warp0 only
            v += __shfl_down_sync(0xffffffffu, v, off);
        if (lane == 0) {
            atomicAdd(&g_acc, v);
            __threadfence();
            unsigned int old = atomicAdd(&g_count, 1u);
            if (old == gridDim.x - 1) {                   // last block: write + reset
                double total = atomicAdd(&g_acc, 0.0);
                out[0] = (float)total;
                g_acc   = 0.0;
                g_count = 0u;
            }
        }
    }
}

// Inputs (metadata order): data[30000], t0[1], tn[1], beta[1], z0[256], v0[12800]
extern "C" void kernel_launch(void* const* d_in, const int* in_sizes, int n_in,
                              void* d_out, int out_size) {
    const float* data = (const float*)d_in[0];
    const float* beta = (const float*)d_in[3];
    const float* z0   = (const float*)d_in[4];
    const float* v0   = (const float*)d_in[5];
    float* out = (float*)d_out;

    prep_kernel<<<4, 1024>>>(data, z0, v0);

    // PDL: overlap main's launch/dispatch with prep's execution
    cudaLaunchConfig_t cfg = {};
    cfg.gridDim  = dim3(MAIN_BLOCKS, 1, 1);
    cfg.blockDim = dim3(MAIN_THREADS, 1, 1);
    cfg.stream   = 0;
    cudaLaunchAttribute attr[1];
    attr[0].id = cudaLaunchAttributeProgrammaticStreamSerialization;
    attr[0].val.programmaticStreamSerializationAllowed = 1;
    cfg.attrs    = attr;
    cfg.numAttrs = 1;
    cudaLaunchKernelEx(&cfg, main_kernel, data, beta, out);
}